// round 6
// baseline (speedup 1.0000x reference)
#include <cuda_runtime.h>
#include <cuda_bf16.h>
#include <math.h>

// Problem dims
#define B_ 256
#define T_ 80
#define E_ 512
#define I_ 1024
#define H_ 1024
#define L_ 300
#define F_ 2048
#define V_ 32000

// ---------------- device scratch (static, no allocation) ----------------
#define OFF_EMB   0                         // B*E
#define OFF_T1    (OFF_EMB  + B_*E_)        // B*4*I
#define OFF_T2    (OFF_T1   + B_*4*I_)      // B*4*I
#define OFF_BASE  (OFF_T2   + B_*4*I_)      // B*4*H
#define OFF_SH    (OFF_BASE + B_*4*H_)      // B*4*I
#define OFF_H     (OFF_SH   + B_*4*I_)      // B*H
#define OFF_C     (OFF_H    + B_*H_)        // B*H
#define OFF_X     (OFF_C    + B_*H_)        // B*4*I
#define SCRATCH_FLOATS (OFF_X + B_*4*I_)

__device__ float g_scratch[SCRATCH_FLOATS];

// ---------------- embedding gather (dtype-robust) ----------------
// captions may be int32 (JAX x64 disabled) or int64. Detect on device:
// for int64 little-endian storage the odd 32-bit words (high halves) are 0.
__global__ void gather_emb_kernel(const float* __restrict__ embed,
                                  const void* __restrict__ captions_raw,
                                  float* __restrict__ emb)
{
    int idx = blockIdx.x * blockDim.x + threadIdx.x;   // B*E
    if (idx >= B_ * E_) return;
    int b = idx / E_;
    int e = idx - b * E_;

    const int* cap32 = (const int*)captions_raw;
    // probe: odd words all zero => int64 storage
    bool is64 = (cap32[1] == 0) && (cap32[3] == 0) && (cap32[5] == 0) && (cap32[7] == 0);

    long long tok;
    if (is64) {
        tok = ((const long long*)captions_raw)[(long long)b * T_];
    } else {
        tok = (long long)cap32[(long long)b * T_];
    }
    if (tok < 0) tok = 0;
    if (tok >= V_) tok = V_ - 1;
    emb[idx] = embed[tok * E_ + e];
}

// ---------------- elementwise kernels ----------------
__global__ void ew_mul_kernel(float* __restrict__ a, const float* __restrict__ b, int n)
{
    int idx = blockIdx.x * blockDim.x + threadIdx.x;
    if (idx < n) a[idx] *= b[idx];
}

__global__ void ew_base_kernel(float* __restrict__ base, const float* __restrict__ vc,
                               const float* __restrict__ bias, int n)
{
    int idx = blockIdx.x * blockDim.x + threadIdx.x;
    if (idx < n) {
        int gh = idx % (4 * H_);
        base[idx] = base[idx] + vc[idx] + bias[gh];
    }
}

__global__ void zero2_kernel(float* __restrict__ a, float* __restrict__ b, int n)
{
    int idx = blockIdx.x * blockDim.x + threadIdx.x;
    if (idx < n) { a[idx] = 0.f; b[idx] = 0.f; }
}

// ---------------- generic tiled GEMM: C[b, g*Npg + n] = sum_k A(b,g,k) * W[g,k,n] ----
// A element (b,g,k) at A[b*asB + g*asG + k]  (asG=0 => gate-shared A)
// Optional elementwise MUL (same layout as C).
// Tile: BM=64, BN=64, BK=16, 256 threads, 4x4 per thread.
__global__ void gemm64_kernel(const float* __restrict__ A, int asB, int asG,
                              const float* __restrict__ W,
                              float* __restrict__ C,
                              const float* __restrict__ MUL,
                              int K, int Npg)
{
    const int ntiles = Npg / 64;
    const int g  = blockIdx.x / ntiles;
    const int n0 = (blockIdx.x % ntiles) * 64;
    const int b0 = blockIdx.y * 64;

    const float* Ab = A + (long long)b0 * asB + (long long)g * asG;
    const float* Wg = W + (long long)g * K * Npg + n0;

    __shared__ float As[16][65];
    __shared__ float Ws[16][64];

    const int tid = threadIdx.x;
    const int tx = tid & 15;        // 0..15 (n)
    const int ty = tid >> 4;        // 0..15 (m)

    float acc[4][4];
    #pragma unroll
    for (int r = 0; r < 4; ++r)
        #pragma unroll
        for (int c = 0; c < 4; ++c) acc[r][c] = 0.f;

    const int ktiles = (K + 15) >> 4;
    for (int kt = 0; kt < ktiles; ++kt) {
        const int k0 = kt * 16;
        // Load A tile: 64 (m) x 16 (k), transposed into As[k][m]
        {
            const int kk   = tid & 15;
            const int mrow = tid >> 4;
            const bool kin = (k0 + kk) < K;
            #pragma unroll
            for (int i = 0; i < 4; ++i) {
                int m = mrow + i * 16;
                float v = 0.f;
                if (kin) v = Ab[(long long)m * asB + k0 + kk];
                As[kk][m] = v;
            }
        }
        // Load W tile: 16 (k) x 64 (n)
        {
            const int nn = tid & 63;
            const int kr = tid >> 6;
            #pragma unroll
            for (int i = 0; i < 4; ++i) {
                int k = kr + i * 4;
                float v = 0.f;
                if (k0 + k < K) v = Wg[(long long)(k0 + k) * Npg + nn];
                Ws[k][nn] = v;
            }
        }
        __syncthreads();
        #pragma unroll
        for (int k = 0; k < 16; ++k) {
            float a[4], wv[4];
            #pragma unroll
            for (int r = 0; r < 4; ++r) a[r] = As[k][ty * 4 + r];
            #pragma unroll
            for (int c = 0; c < 4; ++c) wv[c] = Ws[k][tx * 4 + c];
            #pragma unroll
            for (int r = 0; r < 4; ++r)
                #pragma unroll
                for (int c = 0; c < 4; ++c) acc[r][c] += a[r] * wv[c];
        }
        __syncthreads();
    }

    // Epilogue
    #pragma unroll
    for (int r = 0; r < 4; ++r) {
        const int b = b0 + ty * 4 + r;
        const long long rowbase = (long long)b * 4 * Npg + (long long)g * Npg + n0;
        #pragma unroll
        for (int c = 0; c < 4; ++c) {
            const long long idx = rowbase + tx * 4 + c;
            float v = acc[r][c];
            if (MUL) v *= MUL[idx];
            C[idx] = v;
        }
    }
}

// ---------------- fused stage-2 GEMM + LSTM pointwise ----------------
__device__ __forceinline__ float sigm(float x) { return 1.f / (1.f + expf(-x)); }

__global__ void lstm_step_kernel(const float* __restrict__ X,    // (B,4,I)
                                 const float* __restrict__ Uc,   // (4,I,H)
                                 const float* __restrict__ base, // (B,4,H)
                                 float* __restrict__ h,
                                 float* __restrict__ c,
                                 float* __restrict__ hout)       // extra dest (may be null)
{
    const int n0 = blockIdx.x * 64;   // 16 blocks
    const int b0 = blockIdx.y * 32;   // 8 blocks

    __shared__ float As[16][33];
    __shared__ float Ws[16][64];

    const int tid = threadIdx.x;
    const int tx = tid & 15;   // n, 4 each
    const int ty = tid >> 4;   // 0..15, rows ty*2, ty*2+1

    float acc[4][2][4];
    #pragma unroll
    for (int g = 0; g < 4; ++g)
        #pragma unroll
        for (int r = 0; r < 2; ++r)
            #pragma unroll
            for (int cc = 0; cc < 4; ++cc) acc[g][r][cc] = 0.f;

    for (int g = 0; g < 4; ++g) {
        const float* Ag = X + (long long)b0 * 4 * I_ + (long long)g * I_;
        const float* Wg = Uc + (long long)g * I_ * H_ + n0;
        for (int kt = 0; kt < I_ / 16; ++kt) {
            const int k0 = kt * 16;
            {
                const int kk = tid & 15;
                const int m  = tid >> 4;   // 0..15
                #pragma unroll
                for (int i = 0; i < 2; ++i)
                    As[kk][m + i * 16] = Ag[(long long)(m + i * 16) * 4 * I_ + k0 + kk];
            }
            {
                const int nn = tid & 63;
                const int kr = tid >> 6;
                #pragma unroll
                for (int i = 0; i < 4; ++i)
                    Ws[kr + i * 4][nn] = Wg[(long long)(k0 + kr + i * 4) * H_ + nn];
            }
            __syncthreads();
            #pragma unroll
            for (int k = 0; k < 16; ++k) {
                const float a0 = As[k][ty * 2];
                const float a1 = As[k][ty * 2 + 1];
                float wv[4];
                #pragma unroll
                for (int cc = 0; cc < 4; ++cc) wv[cc] = Ws[k][tx * 4 + cc];
                #pragma unroll
                for (int cc = 0; cc < 4; ++cc) {
                    acc[g][0][cc] += a0 * wv[cc];
                    acc[g][1][cc] += a1 * wv[cc];
                }
            }
            __syncthreads();
        }
    }

    // Epilogue: LSTM pointwise
    #pragma unroll
    for (int r = 0; r < 2; ++r) {
        const int b = b0 + ty * 2 + r;
        const long long bb = (long long)b * 4 * H_;
        #pragma unroll
        for (int cc = 0; cc < 4; ++cc) {
            const int j = n0 + tx * 4 + cc;
            const float ig = sigm(base[bb + 0 * H_ + j] + acc[0][r][cc]);
            const float fg = sigm(base[bb + 1 * H_ + j] + acc[1][r][cc]);
            const float og = sigm(base[bb + 2 * H_ + j] + acc[2][r][cc]);
            const float gg = tanhf(base[bb + 3 * H_ + j] + acc[3][r][cc]);
            const long long hidx = (long long)b * H_ + j;
            const float cn = fg * c[hidx] + ig * gg;
            c[hidx] = cn;
            const float hn = og * tanhf(cn);
            h[hidx] = hn;
            if (hout) hout[hidx] = hn;
        }
    }
}

// ---------------- launch ----------------
extern "C" void kernel_launch(void* const* d_in, const int* in_sizes, int n_in,
                              void* d_out, int out_size)
{
    const void*  captions = d_in[0];           // int32 or int64, detected on device
    const float* cnn   = (const float*)d_in[1];
    const float* sem   = (const float*)d_in[2];
    const float* embed = (const float*)d_in[3];
    const float* Wa    = (const float*)d_in[4];
    const float* Wb    = (const float*)d_in[5];
    const float* Wc    = (const float*)d_in[6];
    const float* Ua    = (const float*)d_in[7];
    const float* Ub    = (const float*)d_in[8];
    const float* Uc    = (const float*)d_in[9];
    const float* Ca    = (const float*)d_in[10];
    const float* Cb    = (const float*)d_in[11];
    const float* Cc    = (const float*)d_in[12];
    const float* bias  = (const float*)d_in[13];
    float* out = (float*)d_out;

    void* sp = nullptr;
    cudaGetSymbolAddress(&sp, g_scratch);
    float* S = (float*)sp;
    float* s_emb  = S + OFF_EMB;
    float* s_t1   = S + OFF_T1;
    float* s_t2   = S + OFF_T2;
    float* s_base = S + OFF_BASE;
    float* s_SH   = S + OFF_SH;
    float* s_h    = S + OFF_H;
    float* s_c    = S + OFF_C;
    float* s_x    = S + OFF_X;

    const dim3 blk(256);
    const dim3 gGemmI(4 * I_ / 64, B_ / 64);   // (64, 4); I_ == H_ so reused for both

    // ---- precompute ----
    gather_emb_kernel<<<(B_ * E_ + 255) / 256, blk>>>(embed, captions, s_emb);

    // Xc = ((emb @ Wa) * (sem @ Wb)) @ Wc
    gemm64_kernel<<<gGemmI, blk>>>(s_emb, E_, 0, Wa, s_t1, nullptr, E_, I_);
    gemm64_kernel<<<gGemmI, blk>>>(sem,  L_, 0, Wb, s_t2, nullptr, L_, I_);
    ew_mul_kernel<<<(B_ * 4 * I_ + 255) / 256, blk>>>(s_t1, s_t2, B_ * 4 * I_);
    gemm64_kernel<<<gGemmI, blk>>>(s_t1, 4 * I_, I_, Wc, s_base, nullptr, I_, H_);

    // Vc = ((cnn @ Ca) * (sem @ Cb)) @ Cc
    gemm64_kernel<<<gGemmI, blk>>>(cnn, F_, 0, Ca, s_t1, nullptr, F_, I_);
    gemm64_kernel<<<gGemmI, blk>>>(sem, L_, 0, Cb, s_t2, nullptr, L_, I_);
    ew_mul_kernel<<<(B_ * 4 * I_ + 255) / 256, blk>>>(s_t1, s_t2, B_ * 4 * I_);
    gemm64_kernel<<<gGemmI, blk>>>(s_t1, 4 * I_, I_, Cc, s_t2, nullptr, I_, H_);

    // base = Xc + Vc + bias
    ew_base_kernel<<<(B_ * 4 * H_ + 255) / 256, blk>>>(s_base, s_t2, bias, B_ * 4 * H_);

    // SH = sem @ Ub
    gemm64_kernel<<<gGemmI, blk>>>(sem, L_, 0, Ub, s_SH, nullptr, L_, I_);

    // h = c = 0
    zero2_kernel<<<(B_ * H_ + 255) / 256, blk>>>(s_h, s_c, B_ * H_);

    // ---- recurrence ----
    const dim3 gLstm(H_ / 64, B_ / 32);  // (16, 8)
    for (int t = 0; t < T_; ++t) {
        // x = (h @ Ua) * SH
        gemm64_kernel<<<gGemmI, blk>>>(s_h, H_, 0, Ua, s_x, s_SH, H_, I_);
        // pre = base + x @ Uc ; gates ; c,h update (write d_out on last step too)
        lstm_step_kernel<<<gLstm, blk>>>(s_x, Uc, s_base, s_h, s_c,
                                         (t == T_ - 1) ? out : nullptr);
    }
}

// round 10
// speedup vs baseline: 2.6690x; 2.6690x over previous
#include <cuda_runtime.h>
#include <cuda_bf16.h>
#include <math.h>
#include <stdint.h>
#include <stddef.h>

// Problem dims
#define B_ 256
#define T_ 80
#define E_ 512
#define I_ 1024
#define H_ 1024
#define L_ 300
#define F_ 2048
#define V_ 32000

// ---------------- fp32 scratch for precompute ----------------
#define OFF_EMB   0
#define OFF_T1    (OFF_EMB  + B_*E_)
#define OFF_T2    (OFF_T1   + B_*4*I_)
#define OFF_BASE  (OFF_T2   + B_*4*I_)
#define OFF_SH    (OFF_BASE + B_*4*H_)
#define SCRATCH_FLOATS (OFF_SH + B_*4*I_)
__device__ float g_scratch[SCRATCH_FLOATS];

// ---------------- recurrence state / converted weights ----------------
// K-stacked bf16 split: A' = [aH | aH | aL] (K=3072) vs W' = [wH | wL | wH]
// => aH*wH + aH*wL + aL*wH  (3-term compensated product, fp32 accumulate)
__device__ float g_c[B_ * H_];                       // [B][1024]
__device__ __nv_bfloat16 g_hStack[B_ * 3072];        // [B][hH|hH|hL]
__device__ __nv_bfloat16 g_xStack[B_ * 4 * 3072];    // [B][g][xH|xH|xL]
__device__ __nv_bfloat16 g_UaS[4096 * 3072];         // [n=g*1024+i][wH|wL|wH], w=Ua[g][k][i]
__device__ __nv_bfloat16 g_UcS[4096 * 3072];         // [n=g*1024+j][wH|wL|wH], w=Uc[g][k][j]

// ======================= low-level helpers ==========================
__device__ __forceinline__ uint32_t smem_u32(const void* p) {
    uint32_t a;
    asm("{ .reg .u64 t; cvta.to.shared.u64 t, %1; cvt.u32.u64 %0, t; }" : "=r"(a) : "l"(p));
    return a;
}
__device__ __forceinline__ void cp16(uint32_t dst, const void* src) {
    asm volatile("cp.async.cg.shared.global [%0], [%1], 16;" :: "r"(dst), "l"(src));
}
__device__ __forceinline__ void cp_commit() { asm volatile("cp.async.commit_group;"); }
__device__ __forceinline__ void cp_wait1()  { asm volatile("cp.async.wait_group 1;" ::: "memory"); }
__device__ __forceinline__ void cp_wait0()  { asm volatile("cp.async.wait_group 0;" ::: "memory"); }

__device__ __forceinline__ void ldsm4(uint32_t* r, uint32_t addr) {
    asm volatile("ldmatrix.sync.aligned.m8n8.x4.shared.b16 {%0,%1,%2,%3}, [%4];"
                 : "=r"(r[0]), "=r"(r[1]), "=r"(r[2]), "=r"(r[3]) : "r"(addr));
}
__device__ __forceinline__ void mma16816(float* d, const uint32_t* a, const uint32_t* b) {
    asm volatile(
        "mma.sync.aligned.m16n8k16.row.col.f32.bf16.bf16.f32 "
        "{%0,%1,%2,%3}, {%4,%5,%6,%7}, {%8,%9}, {%0,%1,%2,%3};"
        : "+f"(d[0]), "+f"(d[1]), "+f"(d[2]), "+f"(d[3])
        : "r"(a[0]), "r"(a[1]), "r"(a[2]), "r"(a[3]), "r"(b[0]), "r"(b[1]));
}
__device__ __forceinline__ float sigm(float x) { return 1.f / (1.f + expf(-x)); }

// smem tile row stride: 64 bf16 = 128B data + 16B pad = 144B (16B-aligned, conflict-free)
#define RS 144

// ================= stage 1: x = (h @ Ua) * SH =================
// GEMM M=256,N=4096,K=3072. BM=64,BN=128,BK=64. 8 warps (2m x 4n), warp tile 32x32.
#define S1_AB   (64 * RS)              /* 9216  */
#define S1_BUF  (S1_AB + 128 * RS)     /* 27648 */
#define S1_SMEM (2 * S1_BUF)           /* 55296 */

__global__ void __launch_bounds__(256, 1) stage1_mma(
    const __nv_bfloat16* __restrict__ hS,   // [B][3072]
    const __nv_bfloat16* __restrict__ WS,   // [4096][3072]
    const float* __restrict__ SH,           // [B][4096]
    __nv_bfloat16* __restrict__ xS)         // [B][12288]
{
    extern __shared__ char smem[];
    const uint32_t sb = smem_u32(smem);
    const int tid = threadIdx.x, lane = tid & 31, wid = tid >> 5;
    const int wm = wid >> 2, wn = wid & 3;
    const int n0 = blockIdx.x * 128, b0 = blockIdx.y * 64;

    auto loadT = [&](int kt, int buf) {
        const uint32_t bA = sb + buf * S1_BUF;
        const uint32_t bB = bA + S1_AB;
        const int k0 = kt * 64;
        #pragma unroll
        for (int i = 0; i < 2; ++i) {                 // A: 64 rows x 4 chunks
            int idx = tid + i * 256, r = idx >> 3, c = idx & 7;
            cp16(bA + r * RS + c * 16, hS + (size_t)(b0 + r) * 3072 + k0 + c * 8);
        }
        #pragma unroll
        for (int i = 0; i < 4; ++i) {                 // B: 128 rows x 4 chunks
            int idx = tid + i * 256, r = idx >> 3, c = idx & 7;
            cp16(bB + r * RS + c * 16, WS + (size_t)(n0 + r) * 3072 + k0 + c * 8);
        }
        cp_commit();
    };

    float acc[2][4][4];
    #pragma unroll
    for (int a = 0; a < 2; ++a)
        #pragma unroll
        for (int b = 0; b < 4; ++b)
            #pragma unroll
            for (int c = 0; c < 4; ++c) acc[a][b][c] = 0.f;

    loadT(0, 0);
    for (int kt = 0; kt < 48; ++kt) {
        if (kt < 47) { loadT(kt + 1, (kt + 1) & 1); cp_wait1(); } else cp_wait0();
        __syncthreads();
        const uint32_t bA = sb + (kt & 1) * S1_BUF, bB = bA + S1_AB;
        #pragma unroll
        for (int kc = 0; kc < 4; ++kc) {
            uint32_t a[2][4], b[2][4];
            #pragma unroll
            for (int mb = 0; mb < 2; ++mb)
                ldsm4(a[mb], bA + (wm * 32 + mb * 16 + (lane & 15)) * RS
                             + kc * 32 + ((lane >> 4) & 1) * 16);
            #pragma unroll
            for (int nb = 0; nb < 2; ++nb)
                ldsm4(b[nb], bB + (wn * 32 + nb * 16 + ((lane >> 4) & 1) * 8 + (lane & 7)) * RS
                             + kc * 32 + ((lane >> 3) & 1) * 16);
            #pragma unroll
            for (int mb = 0; mb < 2; ++mb) {
                mma16816(acc[mb][0], a[mb], b[0] + 0);
                mma16816(acc[mb][1], a[mb], b[0] + 2);
                mma16816(acc[mb][2], a[mb], b[1] + 0);
                mma16816(acc[mb][3], a[mb], b[1] + 2);
            }
        }
        __syncthreads();
    }

    // epilogue: v = acc * SH[b][n]; write stacked bf16 x
    #pragma unroll
    for (int mb = 0; mb < 2; ++mb)
    #pragma unroll
    for (int rh = 0; rh < 2; ++rh) {
        const int b = b0 + wm * 32 + mb * 16 + (lane >> 2) + rh * 8;
        #pragma unroll
        for (int ni = 0; ni < 4; ++ni) {
            const int n = n0 + wn * 32 + ni * 8 + (lane & 3) * 2;
            float2 sh = *(const float2*)(SH + (size_t)b * 4096 + n);
            float v0 = acc[mb][ni][rh * 2 + 0] * sh.x;
            float v1 = acc[mb][ni][rh * 2 + 1] * sh.y;
            __nv_bfloat16 h0 = __float2bfloat16(v0), h1 = __float2bfloat16(v1);
            __nv_bfloat162 hh; hh.x = h0; hh.y = h1;
            __nv_bfloat162 ll;
            ll.x = __float2bfloat16(v0 - __bfloat162float(h0));
            ll.y = __float2bfloat16(v1 - __bfloat162float(h1));
            const int g = n >> 10, i = n & 1023;
            __nv_bfloat16* p = xS + (size_t)b * 12288 + g * 3072 + i;
            *(__nv_bfloat162*)(p)        = hh;
            *(__nv_bfloat162*)(p + 1024) = hh;
            *(__nv_bfloat162*)(p + 2048) = ll;
        }
    }
}

// ===== stage 2: pre = base + x@Uc (all 4 gates in-CTA) ; LSTM pointwise =====
// Per gate: GEMM M=256,N=1024,K=3072. BM=32,BN=64,BK=64. 8 warps (2m x 4n), warp 16x16.
#define S2_AB   (32 * RS)              /* 4608  */
#define S2_BUF  (S2_AB + 64 * RS)      /* 13824 */
#define S2_SMEM (2 * S2_BUF)           /* 27648 */

__global__ void __launch_bounds__(256, 1) stage2_mma(
    const __nv_bfloat16* __restrict__ xS,   // [B][12288]
    const __nv_bfloat16* __restrict__ WS,   // [4096][3072] (row = g*1024 + j)
    const float* __restrict__ base,         // [B][4][1024]
    float* __restrict__ cB,                 // [B][1024]
    __nv_bfloat16* __restrict__ hS,         // [B][3072]
    float* __restrict__ hout)               // null or [B][1024]
{
    extern __shared__ char smem[];
    const uint32_t sb = smem_u32(smem);
    const int tid = threadIdx.x, lane = tid & 31, wid = tid >> 5;
    const int wm = wid >> 2, wn = wid & 3;
    const int n0 = blockIdx.x * 64, b0 = blockIdx.y * 32;

    auto loadT = [&](int g, int kt, int buf) {
        const uint32_t bA = sb + buf * S2_BUF;
        const uint32_t bB = bA + S2_AB;
        const int k0 = kt * 64;
        {                                              // A: 32 rows x 4 chunks = 256
            int r = tid >> 3, c = tid & 7;
            cp16(bA + r * RS + c * 16, xS + (size_t)(b0 + r) * 12288 + g * 3072 + k0 + c * 8);
        }
        #pragma unroll
        for (int i = 0; i < 2; ++i) {                  // B: 64 rows x 4 chunks = 512
            int idx = tid + i * 256, r = idx >> 3, c = idx & 7;
            cp16(bB + r * RS + c * 16, WS + (size_t)(g * 1024 + n0 + r) * 3072 + k0 + c * 8);
        }
        cp_commit();
    };

    float acc[4][2][4];
    #pragma unroll
    for (int a = 0; a < 4; ++a)
        #pragma unroll
        for (int b = 0; b < 2; ++b)
            #pragma unroll
            for (int c = 0; c < 4; ++c) acc[a][b][c] = 0.f;

    loadT(0, 0, 0);
    #pragma unroll
    for (int g = 0; g < 4; ++g) {
        for (int kt = 0; kt < 48; ++kt) {
            const int fj = g * 48 + kt;
            if (fj < 191) {
                const int g2  = (kt == 47) ? g + 1 : g;
                const int kt2 = (kt == 47) ? 0 : kt + 1;
                loadT(g2, kt2, (fj + 1) & 1);
                cp_wait1();
            } else cp_wait0();
            __syncthreads();
            const uint32_t bA = sb + (fj & 1) * S2_BUF, bB = bA + S2_AB;
            #pragma unroll
            for (int kc = 0; kc < 4; ++kc) {
                uint32_t a[4], b[4];
                ldsm4(a, bA + (wm * 16 + (lane & 15)) * RS + kc * 32 + ((lane >> 4) & 1) * 16);
                ldsm4(b, bB + (wn * 16 + ((lane >> 4) & 1) * 8 + (lane & 7)) * RS
                          + kc * 32 + ((lane >> 3) & 1) * 16);
                mma16816(acc[g][0], a, b + 0);
                mma16816(acc[g][1], a, b + 2);
            }
            __syncthreads();
        }
    }

    // epilogue: gates + c/h update
    #pragma unroll
    for (int rh = 0; rh < 2; ++rh) {
        const int b = b0 + wm * 16 + (lane >> 2) + rh * 8;
        #pragma unroll
        for (int ni = 0; ni < 2; ++ni) {
            const int j = n0 + wn * 16 + ni * 8 + (lane & 3) * 2;
            const float* bp = base + (size_t)b * 4096 + j;
            float2 pi = *(const float2*)(bp);
            float2 pf = *(const float2*)(bp + 1024);
            float2 po = *(const float2*)(bp + 2048);
            float2 pg = *(const float2*)(bp + 3072);
            const int e0 = rh * 2, e1 = rh * 2 + 1;
            float i0 = sigm (pi.x + acc[0][ni][e0]), i1 = sigm (pi.y + acc[0][ni][e1]);
            float f0 = sigm (pf.x + acc[1][ni][e0]), f1 = sigm (pf.y + acc[1][ni][e1]);
            float o0 = sigm (po.x + acc[2][ni][e0]), o1 = sigm (po.y + acc[2][ni][e1]);
            float g0 = tanhf(pg.x + acc[3][ni][e0]), g1 = tanhf(pg.y + acc[3][ni][e1]);
            float* cp = cB + (size_t)b * 1024 + j;
            float2 cc = *(float2*)cp;
            float cn0 = f0 * cc.x + i0 * g0;
            float cn1 = f1 * cc.y + i1 * g1;
            float2 cno; cno.x = cn0; cno.y = cn1;
            *(float2*)cp = cno;
            float hn0 = o0 * tanhf(cn0);
            float hn1 = o1 * tanhf(cn1);
            __nv_bfloat16 h0 = __float2bfloat16(hn0), h1 = __float2bfloat16(hn1);
            __nv_bfloat162 hh; hh.x = h0; hh.y = h1;
            __nv_bfloat162 ll;
            ll.x = __float2bfloat16(hn0 - __bfloat162float(h0));
            ll.y = __float2bfloat16(hn1 - __bfloat162float(h1));
            __nv_bfloat16* p = hS + (size_t)b * 3072 + j;
            *(__nv_bfloat162*)(p)        = hh;
            *(__nv_bfloat162*)(p + 1024) = hh;
            *(__nv_bfloat162*)(p + 2048) = ll;
            if (hout) {
                float2 hv; hv.x = hn0; hv.y = hn1;
                *(float2*)(hout + (size_t)b * 1024 + j) = hv;
            }
        }
    }
}

// ======================= precompute kernels (fp32 SIMT) ==========================
__global__ void gather_emb_kernel(const float* __restrict__ embed,
                                  const void* __restrict__ captions_raw,
                                  float* __restrict__ emb)
{
    int idx = blockIdx.x * blockDim.x + threadIdx.x;
    if (idx >= B_ * E_) return;
    int b = idx / E_;
    int e = idx - b * E_;
    const int* cap32 = (const int*)captions_raw;
    bool is64 = (cap32[1] == 0) && (cap32[3] == 0) && (cap32[5] == 0) && (cap32[7] == 0);
    long long tok = is64 ? ((const long long*)captions_raw)[(long long)b * T_]
                         : (long long)cap32[(long long)b * T_];
    if (tok < 0) tok = 0;
    if (tok >= V_) tok = V_ - 1;
    emb[idx] = embed[tok * E_ + e];
}

__global__ void ew_mul_kernel(float* __restrict__ a, const float* __restrict__ b, int n)
{
    int idx = blockIdx.x * blockDim.x + threadIdx.x;
    if (idx < n) a[idx] *= b[idx];
}

__global__ void ew_base_kernel(float* __restrict__ base, const float* __restrict__ vc,
                               const float* __restrict__ bias, int n)
{
    int idx = blockIdx.x * blockDim.x + threadIdx.x;
    if (idx < n) {
        int gh = idx % (4 * H_);
        base[idx] = base[idx] + vc[idx] + bias[gh];
    }
}

__global__ void gemm64_kernel(const float* __restrict__ A, int asB, int asG,
                              const float* __restrict__ W,
                              float* __restrict__ C,
                              int K, int Npg)
{
    const int ntiles = Npg / 64;
    const int g  = blockIdx.x / ntiles;
    const int n0 = (blockIdx.x % ntiles) * 64;
    const int b0 = blockIdx.y * 64;

    const float* Ab = A + (long long)b0 * asB + (long long)g * asG;
    const float* Wg = W + (long long)g * K * Npg + n0;

    __shared__ float As[16][65];
    __shared__ float Ws[16][64];

    const int tid = threadIdx.x;
    const int tx = tid & 15, ty = tid >> 4;

    float acc[4][4];
    #pragma unroll
    for (int r = 0; r < 4; ++r)
        #pragma unroll
        for (int c = 0; c < 4; ++c) acc[r][c] = 0.f;

    const int ktiles = (K + 15) >> 4;
    for (int kt = 0; kt < ktiles; ++kt) {
        const int k0 = kt * 16;
        {
            const int kk = tid & 15, mrow = tid >> 4;
            const bool kin = (k0 + kk) < K;
            #pragma unroll
            for (int i = 0; i < 4; ++i) {
                int m = mrow + i * 16;
                As[kk][m] = kin ? Ab[(long long)m * asB + k0 + kk] : 0.f;
            }
        }
        {
            const int nn = tid & 63, kr = tid >> 6;
            #pragma unroll
            for (int i = 0; i < 4; ++i) {
                int k = kr + i * 4;
                Ws[k][nn] = (k0 + k < K) ? Wg[(long long)(k0 + k) * Npg + nn] : 0.f;
            }
        }
        __syncthreads();
        #pragma unroll
        for (int k = 0; k < 16; ++k) {
            float a[4], wv[4];
            #pragma unroll
            for (int r = 0; r < 4; ++r) a[r] = As[k][ty * 4 + r];
            #pragma unroll
            for (int c = 0; c < 4; ++c) wv[c] = Ws[k][tx * 4 + c];
            #pragma unroll
            for (int r = 0; r < 4; ++r)
                #pragma unroll
                for (int c = 0; c < 4; ++c) acc[r][c] += a[r] * wv[c];
        }
        __syncthreads();
    }
    #pragma unroll
    for (int r = 0; r < 4; ++r) {
        const int b = b0 + ty * 4 + r;
        const long long rowbase = (long long)b * 4 * Npg + (long long)g * Npg + n0;
        #pragma unroll
        for (int c = 0; c < 4; ++c) C[rowbase + tx * 4 + c] = acc[r][c];
    }
}

// W [4][1024(k)][1024(n)] -> S [4096(n=g*1024+n)][3072] with [wH | wL | wH] stacking
__global__ void wprep_kernel(const float* __restrict__ W, __nv_bfloat16* __restrict__ o)
{
    __shared__ float t[32][33];
    const int g = blockIdx.z;
    const int c0 = blockIdx.x * 32, r0 = blockIdx.y * 32;   // c = n, r = k
    const float* in = W + (size_t)g * 1048576;
    for (int i = threadIdx.y; i < 32; i += 8)
        t[i][threadIdx.x] = in[(size_t)(r0 + i) * 1024 + c0 + threadIdx.x];
    __syncthreads();
    for (int i = threadIdx.y; i < 32; i += 8) {
        float v = t[threadIdx.x][i];                 // = W[g][r0+tx][c0+i]
        __nv_bfloat16 h = __float2bfloat16(v);
        __nv_bfloat16 l = __float2bfloat16(v - __bfloat162float(h));
        size_t row = (size_t)(g * 1024 + c0 + i) * 3072;
        size_t k = r0 + threadIdx.x;
        o[row + k]        = h;
        o[row + 1024 + k] = l;
        o[row + 2048 + k] = h;
    }
}

__global__ void init_state_kernel(float* __restrict__ c, __nv_bfloat16* __restrict__ hS)
{
    int i = blockIdx.x * blockDim.x + threadIdx.x;
    if (i < B_ * H_) c[i] = 0.f;
    if (i < B_ * 3072) hS[i] = __float2bfloat16(0.f);
}

// ======================= launch ==========================
extern "C" void kernel_launch(void* const* d_in, const int* in_sizes, int n_in,
                              void* d_out, int out_size)
{
    const void*  captions = d_in[0];
    const float* cnn   = (const float*)d_in[1];
    const float* sem   = (const float*)d_in[2];
    const float* embed = (const float*)d_in[3];
    const float* Wa    = (const float*)d_in[4];
    const float* Wb    = (const float*)d_in[5];
    const float* Wc    = (const float*)d_in[6];
    const float* Ua    = (const float*)d_in[7];
    const float* Ub    = (const float*)d_in[8];
    const float* Uc    = (const float*)d_in[9];
    const float* Ca    = (const float*)d_in[10];
    const float* Cb    = (const float*)d_in[11];
    const float* Cc    = (const float*)d_in[12];
    const float* bias  = (const float*)d_in[13];
    float* out = (float*)d_out;

    cudaFuncSetAttribute(stage1_mma, cudaFuncAttributeMaxDynamicSharedMemorySize, S1_SMEM);
    cudaFuncSetAttribute(stage2_mma, cudaFuncAttributeMaxDynamicSharedMemorySize, S2_SMEM);

    void* p;
    cudaGetSymbolAddress(&p, g_scratch); float* S = (float*)p;
    float* s_emb  = S + OFF_EMB;
    float* s_t1   = S + OFF_T1;
    float* s_t2   = S + OFF_T2;
    float* s_base = S + OFF_BASE;
    float* s_SH   = S + OFF_SH;
    cudaGetSymbolAddress(&p, g_c);      float* cB = (float*)p;
    cudaGetSymbolAddress(&p, g_hStack); __nv_bfloat16* hS  = (__nv_bfloat16*)p;
    cudaGetSymbolAddress(&p, g_xStack); __nv_bfloat16* xS  = (__nv_bfloat16*)p;
    cudaGetSymbolAddress(&p, g_UaS);    __nv_bfloat16* UaS = (__nv_bfloat16*)p;
    cudaGetSymbolAddress(&p, g_UcS);    __nv_bfloat16* UcS = (__nv_bfloat16*)p;

    const dim3 blk(256);
    const dim3 gGemmI(4 * I_ / 64, B_ / 64);

    // ---- precompute (fp32) ----
    gather_emb_kernel<<<(B_ * E_ + 255) / 256, blk>>>(embed, captions, s_emb);

    gemm64_kernel<<<gGemmI, blk>>>(s_emb, E_, 0, Wa, s_t1, E_, I_);
    gemm64_kernel<<<gGemmI, blk>>>(sem,  L_, 0, Wb, s_t2, L_, I_);
    ew_mul_kernel<<<(B_ * 4 * I_ + 255) / 256, blk>>>(s_t1, s_t2, B_ * 4 * I_);
    gemm64_kernel<<<gGemmI, blk>>>(s_t1, 4 * I_, I_, Wc, s_base, I_, H_);

    gemm64_kernel<<<gGemmI, blk>>>(cnn, F_, 0, Ca, s_t1, F_, I_);
    gemm64_kernel<<<gGemmI, blk>>>(sem, L_, 0, Cb, s_t2, L_, I_);
    ew_mul_kernel<<<(B_ * 4 * I_ + 255) / 256, blk>>>(s_t1, s_t2, B_ * 4 * I_);
    gemm64_kernel<<<gGemmI, blk>>>(s_t1, 4 * I_, I_, Cc, s_t2, I_, H_);

    ew_base_kernel<<<(B_ * 4 * H_ + 255) / 256, blk>>>(s_base, s_t2, bias, B_ * 4 * H_);
    gemm64_kernel<<<gGemmI, blk>>>(sem, L_, 0, Ub, s_SH, L_, I_);

    // weight split/stack + state init
    wprep_kernel<<<dim3(32, 32, 4), dim3(32, 8)>>>(Ua, UaS);
    wprep_kernel<<<dim3(32, 32, 4), dim3(32, 8)>>>(Uc, UcS);
    init_state_kernel<<<(B_ * 3072 + 255) / 256, blk>>>(cB, hS);

    // ---- recurrence (bf16 hi/lo split HMMA) ----
    for (int t = 0; t < T_; ++t) {
        stage1_mma<<<dim3(32, 4), blk, S1_SMEM>>>(hS, UaS, s_SH, xS);
        stage2_mma<<<dim3(16, 8), blk, S2_SMEM>>>(xS, UcS, s_base, cB, hS,
                                                  (t == T_ - 1) ? out : nullptr);
    }
}